// round 15
// baseline (speedup 1.0000x reference)
#include <cuda_runtime.h>
#include <cuda_fp16.h>
#include <cstdint>

// Problem constants
#define BB 16
#define TT 4096
#define DD 768
#define NBOX 1024
#define MAXB 128
#define DDETR 256
#define VIS_ELEMS (BB*MAXB*DD)
#define MASK_ELEMS (BB*MAXB)
#define NC 64
#define SPLITK 4

// ---------------- scratch (device globals) -----------------------------------
__device__ __align__(16) float g_partial[BB*NC*DD];
__device__ __align__(16) float g_x[BB*DD];
__device__ __align__(16) float g_h1t[BB*DD];
__device__ __align__(16) float g_h1d[BB*DD];
__device__ __align__(16) float g_xt[BB*DD];
__device__ __align__(16) float g_hb[BB*DD];
__device__ __align__(16) float g_haccs[SPLITK*NBOX*DD];   // gemm2 partials
__device__ __align__(16) float g_wcaccs[SPLITK*768*768];  // gemmWC partials
__device__ __align__(16) float g_cb[DD];                  // pw2 @ m2b
__device__ int g_pos[NBOX];
__device__ int g_counts[BB];

// fp16 hi/lo operand arrays (row-major, k contiguous)
__device__ __align__(16) __half g_w1h[768*256],  g_w1l[768*256];
__device__ __align__(16) __half g_wph[768*768],  g_wpl[768*768];   // pw[:,768:]
__device__ __align__(16) __half g_w2th[768*768], g_w2tl[768*768];  // m2w^T
__device__ __align__(16) __half g_wch[768*768],  g_wcl[768*768];   // WC = pw2@m2w
__device__ __align__(16) __half g_feath[1024*256], g_featl[1024*256];
__device__ __align__(16) __half g_fm1h[1024*768],  g_fm1l[1024*768];

// ---------------- helpers -------------------------------------------------------
__device__ __forceinline__ uint32_t smem_u32(const void* p) {
    uint32_t r;
    asm("{ .reg .u64 t; cvta.to.shared.u64 t, %1; cvt.u32.u64 %0, t; }"
        : "=r"(r) : "l"(p));
    return r;
}
#define CP_ASYNC16(dst, src) \
    asm volatile("cp.async.cg.shared.global [%0], [%1], 16;" \
                 :: "r"(dst), "l"(src) : "memory")
#define CP_COMMIT() asm volatile("cp.async.commit_group;" ::: "memory")
#define CP_WAIT(n)  asm volatile("cp.async.wait_group %0;" :: "n"(n) : "memory")

#define LDSM_X4(r0, r1, r2, r3, addr) \
    asm volatile("ldmatrix.sync.aligned.m8n8.x4.shared.b16 {%0,%1,%2,%3}, [%4];" \
                 : "=r"(r0), "=r"(r1), "=r"(r2), "=r"(r3) : "r"(addr))

#define MMA16816(acc, a0, a1, a2, a3, b0, b1) \
    asm volatile("mma.sync.aligned.m16n8k16.row.col.f32.f16.f16.f32 " \
                 "{%0,%1,%2,%3}, {%4,%5,%6,%7}, {%8,%9}, {%0,%1,%2,%3};" \
                 : "+f"((acc)[0]), "+f"((acc)[1]), "+f"((acc)[2]), "+f"((acc)[3]) \
                 : "r"(a0), "r"(a1), "r"(a2), "r"(a3), "r"(b0), "r"(b1))

__device__ __forceinline__ void h2split(float v, __half2* oh, __half2* ol,
                                        float v1) {
    __half h0 = __float2half_rn(v),  h1 = __float2half_rn(v1);
    __half l0 = __float2half_rn(v - __half2float(h0));
    __half l1 = __float2half_rn(v1 - __half2float(h1));
    *oh = __halves2half2(h0, h1);
    *ol = __halves2half2(l0, l1);
}

// ---------------- segment metadata (tiny) ----------------------------------------
__global__ void meta_kernel(const int* __restrict__ bboxes,
                            float* __restrict__ att_mask_out) {
    __shared__ int counts[BB];
    __shared__ int offs[BB];
    int t = threadIdx.x;
    if (t < BB) counts[t] = 0;
    __syncthreads();
    int im = bboxes[t * 5];
    atomicAdd(&counts[im], 1);
    __syncthreads();
    if (t == 0) {
        int s = 0;
        for (int b = 0; b < BB; b++) { offs[b] = s; s += counts[b]; }
    }
    __syncthreads();
    g_pos[t] = t - offs[im];
    if (t < BB) g_counts[t] = counts[t];
    for (int i = t; i < BB * MAXB; i += NBOX) {
        int b = i / MAXB, m = i % MAXB;
        att_mask_out[i] = (m < counts[b]) ? 1.0f : 0.0f;
    }
}

// ---------------- zero ONLY complement slots -------------------------------------
__global__ void zero_comp_kernel(float4* __restrict__ out) {
    const int n4 = VIS_ELEMS / 4;
    for (int i = blockIdx.x * blockDim.x + threadIdx.x; i < n4;
         i += gridDim.x * blockDim.x) {
        int row = i / 192;
        int b = row >> 7, m = row & 127;
        if (m >= g_counts[b])
            out[i] = make_float4(0.f, 0.f, 0.f, 0.f);
    }
}

// ---------------- epilogue: vis[img,pos] = sum_z hacc[z] + hb[img] + cb ----------
__global__ void epi_kernel(const int* __restrict__ bboxes,
                           float* __restrict__ out_vis) {
    int n = blockIdx.x;
    int p = g_pos[n];
    if (p >= MAXB) return;
    int im = bboxes[n * 5];
    int c4 = threadIdx.x * 4;
    float4 a = make_float4(0.f, 0.f, 0.f, 0.f);
#pragma unroll
    for (int z = 0; z < SPLITK; z++) {
        float4 t = *reinterpret_cast<const float4*>(
            &g_haccs[(size_t)z * NBOX * DD + (size_t)n * DD + c4]);
        a.x += t.x; a.y += t.y; a.z += t.z; a.w += t.w;
    }
    float4 b = *reinterpret_cast<const float4*>(&g_hb[im * DD + c4]);
    float4 c = *reinterpret_cast<const float4*>(&g_cb[c4]);
    a.x += b.x + c.x; a.y += b.y + c.y; a.z += b.z + c.z; a.w += b.w + c.w;
    *reinterpret_cast<float4*>(&out_vis[((size_t)im * MAXB + p) * DD + c4]) = a;
}

// ---------------- mean pass 1 ----------------------------------------------------
__global__ void mean_partial_kernel(const float* __restrict__ in) {
    int b = blockIdx.x >> 6;
    int c = blockIdx.x & 63;
    const float4* p = reinterpret_cast<const float4*>(
        in + ((size_t)b * TT + (size_t)c * 64) * DD) + threadIdx.x;
    float4 acc = make_float4(0.f, 0.f, 0.f, 0.f);
    #pragma unroll 8
    for (int r = 0; r < 64; r++) {
        float4 v = p[(size_t)r * (DD / 4)];
        acc.x += v.x; acc.y += v.y; acc.z += v.z; acc.w += v.w;
    }
    reinterpret_cast<float4*>(g_partial + ((size_t)b * NC + c) * DD)[threadIdx.x] = acc;
}

// ---------------- mean pass 2: warp per float4 output ----------------------------
__global__ void mean_final_kernel() {
    int W = blockIdx.x * 8 + (threadIdx.x >> 5);
    int lane = threadIdx.x & 31;
    int b  = W / 192;
    int c4 = W - b * 192;
    const float4* base = reinterpret_cast<const float4*>(g_partial)
                         + (size_t)b * NC * 192 + c4;
    float4 v0 = base[(size_t)lane * 192];
    float4 v1 = base[(size_t)(lane + 32) * 192];
    float sx = v0.x + v1.x, sy = v0.y + v1.y, sz = v0.z + v1.z, sw = v0.w + v1.w;
#pragma unroll
    for (int off = 16; off > 0; off >>= 1) {
        sx += __shfl_xor_sync(0xFFFFFFFFu, sx, off);
        sy += __shfl_xor_sync(0xFFFFFFFFu, sy, off);
        sz += __shfl_xor_sync(0xFFFFFFFFu, sz, off);
        sw += __shfl_xor_sync(0xFFFFFFFFu, sw, off);
    }
    if (lane == 0) {
        const float s = 1.0f / (float)TT;
        reinterpret_cast<float4*>(g_x)[(size_t)b * 192 + c4] =
            make_float4(sx * s, sy * s, sz * s, sw * s);
    }
}

// ---------------- small GEMV: no smem staging, k-split 2, grid 192 ----------------
__global__ __launch_bounds__(256) void mlp2_kernel(
        const float* __restrict__ in, const float* __restrict__ w,
        const float* __restrict__ bias, float* __restrict__ out,
        int do_relu, int wstride) {
    __shared__ float sp[4][2][BB];
    const int tid = threadIdx.x, warp = tid >> 5, lane = tid & 31;
    const int col = warp >> 1, kh = warp & 1;
    const int j = blockIdx.x * 4 + col;
    const float* wr = w + (size_t)j * wstride + kh * 384;

    float4 wv[3];
#pragma unroll
    for (int i = 0; i < 3; i++)
        wv[i] = *reinterpret_cast<const float4*>(&wr[i * 128 + lane * 4]);

    float acc[BB];
#pragma unroll
    for (int b = 0; b < BB; b++) acc[b] = 0.f;
#pragma unroll
    for (int i = 0; i < 3; i++) {
        int k = kh * 384 + i * 128 + lane * 4;
#pragma unroll
        for (int b = 0; b < BB; b++) {
            float4 xv = __ldg(reinterpret_cast<const float4*>(&in[b * DD + k]));
            acc[b] = fmaf(wv[i].x, xv.x, acc[b]);
            acc[b] = fmaf(wv[i].y, xv.y, acc[b]);
            acc[b] = fmaf(wv[i].z, xv.z, acc[b]);
            acc[b] = fmaf(wv[i].w, xv.w, acc[b]);
        }
    }
#pragma unroll
    for (int b = 0; b < BB; b++) {
#pragma unroll
        for (int off = 16; off > 0; off >>= 1)
            acc[b] += __shfl_xor_sync(0xFFFFFFFFu, acc[b], off);
    }
    if (lane == 0) {
#pragma unroll
        for (int b = 0; b < BB; b++) sp[col][kh][b] = acc[b];
    }
    __syncthreads();
    if (tid < 64) {
        int c = tid >> 4, b = tid & 15;
        int jj = blockIdx.x * 4 + c;
        float v = sp[c][0][b] + sp[c][1][b] + bias[jj];
        if (do_relu) v = fmaxf(v, 0.f);
        out[b * DD + jj] = v;
    }
}

// ---------------- cb = pw2 @ m2b (warp per output) --------------------------------
__global__ void cb_kernel(const float* __restrict__ pw,
                          const float* __restrict__ m2b) {
    int warp = threadIdx.x >> 5, lane = threadIdx.x & 31;
    int j = blockIdx.x * 8 + warp;
    const float* wr = pw + (size_t)j * (2 * DD) + DD;
    float acc = 0.f;
#pragma unroll
    for (int i = 0; i < 6; i++) {
        float4 w4 = *reinterpret_cast<const float4*>(&wr[i * 128 + lane * 4]);
        float4 b4 = *reinterpret_cast<const float4*>(&m2b[i * 128 + lane * 4]);
        acc += w4.x * b4.x + w4.y * b4.y + w4.z * b4.z + w4.w * b4.w;
    }
#pragma unroll
    for (int off = 16; off > 0; off >>= 1)
        acc += __shfl_xor_sync(0xFFFFFFFFu, acc, off);
    if (lane == 0) g_cb[j] = acc;
}

// ---------------- convert: w1 + feat split ----------------------------------------
#define CN1 (768*256)
#define CN4 (1024*256)
__global__ void conv0_kernel(const float* __restrict__ m1w,
                             const float* __restrict__ feat) {
    const int TOT = CN1 + CN4;
    for (int i = blockIdx.x * blockDim.x + threadIdx.x; i < TOT;
         i += gridDim.x * blockDim.x) {
        float v; __half *oh, *ol; int o;
        if (i < CN1) { o = i; v = m1w[o]; oh = g_w1h; ol = g_w1l; }
        else {
            o = i - CN1;
            int n = o >> 8, k = o & 255;
            v = feat[(size_t)n * (DDETR + 1) + 1 + k];
            oh = g_feath; ol = g_featl;
        }
        __half h = __float2half_rn(v);
        oh[o] = h;
        ol[o] = __float2half_rn(v - __half2float(h));
    }
}
// ---------------- convert: pw2 split ----------------------------------------------
__global__ void convp_kernel(const float* __restrict__ pw) {
    const int TOT = 768 * 768;
    for (int i = blockIdx.x * blockDim.x + threadIdx.x; i < TOT;
         i += gridDim.x * blockDim.x) {
        int col = i / 768, k = i - col * 768;
        float v = pw[(size_t)col * (2 * DD) + DD + k];
        __half h = __float2half_rn(v);
        g_wph[i] = h;
        g_wpl[i] = __float2half_rn(v - __half2float(h));
    }
}
// ---------------- transpose + split m2w -> g_w2th/g_w2tl --------------------------
__global__ void w2t_kernel(const float* __restrict__ m2w) {
    __shared__ float tile[32][33];
    int bx = blockIdx.x, by = blockIdx.y;
    int tx = threadIdx.x & 31, tr = threadIdx.x >> 5;
    for (int r = tr; r < 32; r += 8)
        tile[r][tx] = m2w[(size_t)(by * 32 + r) * 768 + bx * 32 + tx];
    __syncthreads();
    for (int r = tr; r < 32; r += 8) {
        float v = tile[tx][r];
        size_t o = (size_t)(bx * 32 + r) * 768 + by * 32 + tx;
        __half h = __float2half_rn(v);
        g_w2th[o] = h;
        g_w2tl[o] = __float2half_rn(v - __half2float(h));
    }
}

// ---------------- WC reduce: sum partials, split to hi/lo -------------------------
__global__ void wcsplit_kernel() {
    const int TOT = 768 * 768;
    for (int i = blockIdx.x * blockDim.x + threadIdx.x; i < TOT;
         i += gridDim.x * blockDim.x) {
        float v = 0.f;
#pragma unroll
        for (int z = 0; z < SPLITK; z++)
            v += g_wcaccs[(size_t)z * 768 * 768 + i];
        __half h = __float2half_rn(v);
        g_wch[i] = h;
        g_wcl[i] = __float2half_rn(v - __half2float(h));
    }
}

// ---------------- fp16 split GEMM: 2-stage cp.async, split-K via blockIdx.z --------
// mode 0: fm1 = relu(feat @ m1w^T + m1b)   K=256, grid(16,12,1) -> hi/lo
// mode 2: haccs[z] = fm1 @ WC^T (K/4)      K=768, grid(16,12,4) -> raw fp32
// mode 3: wcaccs[z] = pw2 @ m2wT (K/4)     K=768, grid(12,12,4) -> raw fp32
#define NSTG 2
#define ARRB (64*20*4)
#define STGB (4*ARRB)
#define GEMM_SMEM (NSTG*STGB)    // 40960 -> 5 blocks/SM
__global__ __launch_bounds__(256) void hgemm(int mode,
        const float* __restrict__ bias) {
    extern __shared__ __align__(16) uint32_t S[];

    const int tid = threadIdx.x;
    const int bm = blockIdx.x, bn = blockIdx.y, bz = blockIdx.z;
    const int wid = tid >> 5, lane = tid & 31, gid = lane >> 2, tig = lane & 3;
    const int wm = wid >> 2, wn = wid & 3;
    const int K = (mode == 0) ? 256 : 768;
    const int K2 = K >> 1;                       // row stride in uint32
    const int Keff = K / gridDim.z;
    const int nch = Keff / 32;
    const int kb2 = bz * (Keff >> 1);            // k offset in uint32

    const __half *Ahp, *Alp, *Bhp, *Blp;
    if (mode == 0)      { Ahp = g_feath; Alp = g_featl; Bhp = g_w1h;  Blp = g_w1l;  }
    else if (mode == 2) { Ahp = g_fm1h;  Alp = g_fm1l;  Bhp = g_wch;  Blp = g_wcl;  }
    else                { Ahp = g_wph;   Alp = g_wpl;   Bhp = g_w2th; Blp = g_w2tl; }

    const uint32_t* gsrc[4];
    gsrc[0] = (const uint32_t*)Ahp + (size_t)(bm * 64) * K2 + kb2;
    gsrc[1] = (const uint32_t*)Alp + (size_t)(bm * 64) * K2 + kb2;
    gsrc[2] = (const uint32_t*)Bhp + (size_t)(bn * 64) * K2 + kb2;
    gsrc[3] = (const uint32_t*)Blp + (size_t)(bn * 64) * K2 + kb2;

    const uint32_t sbase = smem_u32(S);

    const int q = lane >> 3, lm = lane & 7;
    const uint32_t offA = (uint32_t)(((wm * 32 + lm + (q & 1) * 8) * 20
                                      + ((q >> 1) * 4)) * 4);
    const uint32_t offB = (uint32_t)(((wn * 16 + lm + (q >> 1) * 8) * 20
                                      + ((q & 1) * 4)) * 4);

    float acc[2][2][4];
#pragma unroll
    for (int mt = 0; mt < 2; mt++)
#pragma unroll
        for (int nt = 0; nt < 2; nt++)
#pragma unroll
            for (int x = 0; x < 4; x++) acc[mt][nt][x] = 0.f;

#define LOAD_CHUNK(ch, st) do {                                              \
        int _kc2 = (ch) * 16;                                                \
        _Pragma("unroll")                                                    \
        for (int _i = 0; _i < 4; _i++) {                                     \
            int _id = tid + _i * 256;                                        \
            int _arr = _id >> 8;                                             \
            int _rem = _id & 255;                                            \
            int _row = _rem >> 2, _seg = _rem & 3;                           \
            const uint32_t* _gp = gsrc[_arr] + (size_t)_row * K2 + _kc2 + _seg * 4; \
            uint32_t _dst = sbase + (st) * STGB + _arr * ARRB                \
                            + (_row * 20 + _seg * 4) * 4;                    \
            CP_ASYNC16(_dst, _gp);                                           \
        }                                                                    \
    } while (0)

    LOAD_CHUNK(0, 0);
    CP_COMMIT();

    for (int c = 0; c < nch; c++) {
        const int buf = c & 1;
        if (c + 1 < nch) {
            LOAD_CHUNK(c + 1, buf ^ 1);
            CP_COMMIT();
            CP_WAIT(1);
        } else {
            CP_WAIT(0);
        }
        __syncthreads();

        const uint32_t stb = sbase + buf * STGB;
#pragma unroll
        for (int ks = 0; ks < 2; ks++) {
            uint32_t ah0[4], ah1[4], al0[4], al1[4], bh[4], bl[4];
            LDSM_X4(ah0[0], ah0[1], ah0[2], ah0[3], stb + offA + ks * 32);
            LDSM_X4(ah1[0], ah1[1], ah1[2], ah1[3], stb + offA + 1280 + ks * 32);
            LDSM_X4(al0[0], al0[1], al0[2], al0[3], stb + ARRB + offA + ks * 32);
            LDSM_X4(al1[0], al1[1], al1[2], al1[3], stb + ARRB + offA + 1280 + ks * 32);
            LDSM_X4(bh[0],  bh[1],  bh[2],  bh[3],  stb + 2 * ARRB + offB + ks * 32);
            LDSM_X4(bl[0],  bl[1],  bl[2],  bl[3],  stb + 3 * ARRB + offB + ks * 32);
#pragma unroll
            for (int nt = 0; nt < 2; nt++) {
                uint32_t b0 = bh[nt * 2], b1 = bh[nt * 2 + 1];
                uint32_t c0 = bl[nt * 2], c1 = bl[nt * 2 + 1];
                MMA16816(acc[0][nt], ah0[0], ah0[1], ah0[2], ah0[3], b0, b1);
                MMA16816(acc[1][nt], ah1[0], ah1[1], ah1[2], ah1[3], b0, b1);
                MMA16816(acc[0][nt], al0[0], al0[1], al0[2], al0[3], b0, b1);
                MMA16816(acc[1][nt], al1[0], al1[1], al1[2], al1[3], b0, b1);
                MMA16816(acc[0][nt], ah0[0], ah0[1], ah0[2], ah0[3], c0, c1);
                MMA16816(acc[1][nt], ah1[0], ah1[1], ah1[2], ah1[3], c0, c1);
            }
        }
        __syncthreads();
    }
#undef LOAD_CHUNK

    const int col00 = bn * 64 + wn * 16;
    if (mode != 0) {
        float* dst = (mode == 2) ? &g_haccs[(size_t)bz * NBOX * DD]
                                 : &g_wcaccs[(size_t)bz * 768 * 768];
#pragma unroll
        for (int nt = 0; nt < 2; nt++) {
            int col = col00 + nt * 8 + tig * 2;
#pragma unroll
            for (int mt = 0; mt < 2; mt++) {
                int r = bm * 64 + wm * 32 + mt * 16 + gid;
                float* d0 = &dst[(size_t)r * DD + col];
                d0[0] = acc[mt][nt][0];
                d0[1] = acc[mt][nt][1];
                float* d1 = &dst[(size_t)(r + 8) * DD + col];
                d1[0] = acc[mt][nt][2];
                d1[1] = acc[mt][nt][3];
            }
        }
    } else {
#pragma unroll
        for (int nt = 0; nt < 2; nt++) {
            int col = col00 + nt * 8 + tig * 2;
            float bv0 = bias[col], bv1 = bias[col + 1];
#pragma unroll
            for (int mt = 0; mt < 2; mt++) {
                int r = bm * 64 + wm * 32 + mt * 16 + gid;
                float v00 = fmaxf(acc[mt][nt][0] + bv0, 0.f);
                float v01 = fmaxf(acc[mt][nt][1] + bv1, 0.f);
                float v10 = fmaxf(acc[mt][nt][2] + bv0, 0.f);
                float v11 = fmaxf(acc[mt][nt][3] + bv1, 0.f);
                __half2 hp, lp;
                h2split(v00, &hp, &lp, v01);
                *(__half2*)&g_fm1h[(size_t)r * DD + col] = hp;
                *(__half2*)&g_fm1l[(size_t)r * DD + col] = lp;
                h2split(v10, &hp, &lp, v11);
                *(__half2*)&g_fm1h[(size_t)(r + 8) * DD + col] = hp;
                *(__half2*)&g_fm1l[(size_t)(r + 8) * DD + col] = lp;
            }
        }
    }
}

// ---------------- launch: 3-stream graph, split-K x4 GEMMs -------------------------
extern "C" void kernel_launch(void* const* d_in, const int* in_sizes, int n_in,
                              void* d_out, int out_size) {
    (void)in_sizes; (void)n_in; (void)out_size;
    const float* inputs   = (const float*)d_in[0];
    const int*   bboxes   = (const int*)  d_in[1];
    const float* features = (const float*)d_in[2];
    const float* t1w = (const float*)d_in[3],  *t1b = (const float*)d_in[4];
    const float* t2w = (const float*)d_in[5],  *t2b = (const float*)d_in[6];
    const float* d1w = (const float*)d_in[7],  *d1b = (const float*)d_in[8];
    const float* d2w = (const float*)d_in[9],  *d2b = (const float*)d_in[10];
    const float* m1w = (const float*)d_in[11], *m1b = (const float*)d_in[12];
    const float* m2w = (const float*)d_in[13], *m2b = (const float*)d_in[14];
    const float* pw  = (const float*)d_in[15], *pb  = (const float*)d_in[16];

    float* out      = (float*)d_out;
    float* out_vis  = out;
    float* out_mask = out + VIS_ELEMS;
    float* out_retx = out + VIS_ELEMS + MASK_ELEMS;

    cudaFuncSetAttribute(hgemm, cudaFuncAttributeMaxDynamicSharedMemorySize,
                         GEMM_SMEM);

    static cudaStream_t s2 = nullptr, s3 = nullptr;
    static cudaEvent_t eFork = nullptr, eMean = nullptr, eMeta = nullptr,
                       eB = nullptr, eC = nullptr, eWC = nullptr;
    static float *p_x, *p_h1t, *p_h1d, *p_xt, *p_hb;
    if (s2 == nullptr) {
        cudaStreamCreateWithFlags(&s2, cudaStreamNonBlocking);
        cudaStreamCreateWithFlags(&s3, cudaStreamNonBlocking);
        cudaEventCreateWithFlags(&eFork, cudaEventDisableTiming);
        cudaEventCreateWithFlags(&eMean, cudaEventDisableTiming);
        cudaEventCreateWithFlags(&eMeta, cudaEventDisableTiming);
        cudaEventCreateWithFlags(&eB, cudaEventDisableTiming);
        cudaEventCreateWithFlags(&eC, cudaEventDisableTiming);
        cudaEventCreateWithFlags(&eWC, cudaEventDisableTiming);
        cudaGetSymbolAddress((void**)&p_x,    g_x);
        cudaGetSymbolAddress((void**)&p_h1t,  g_h1t);
        cudaGetSymbolAddress((void**)&p_h1d,  g_h1d);
        cudaGetSymbolAddress((void**)&p_xt,   g_xt);
        cudaGetSymbolAddress((void**)&p_hb,   g_hb);
    }

    // fork
    cudaEventRecord(eFork, 0);
    cudaStreamWaitEvent(s2, eFork, 0);
    cudaStreamWaitEvent(s3, eFork, 0);

    // launch order puts the split-K gemmWC 6th (profiled by ncu -s 5 -c 1)
    mean_partial_kernel<<<BB * NC, 192, 0, s2>>>(inputs);            // 1 (B)
    convp_kernel<<<384, 256, 0, s3>>>(pw);                           // 2 (C)
    w2t_kernel<<<dim3(24, 24), 256, 0, s3>>>(m2w);                   // 3 (C)
    mean_final_kernel<<<384, 256, 0, s2>>>();                        // 4 (B)
    cudaEventRecord(eMean, s2);
    cb_kernel<<<96, 256, 0, s3>>>(pw, m2b);                          // 5 (C)
    hgemm<<<dim3(12, 12, SPLITK), 256, GEMM_SMEM, s3>>>(3, nullptr); // 6 (C) <- prof
    wcsplit_kernel<<<576, 256, 0, s3>>>();                           // 7 (C)
    cudaEventRecord(eWC, s3);

    // ---- stream B: t-chain -> hb ----
    mlp2_kernel<<<192, 256, 0, s2>>>(p_x,   t1w, t1b, p_h1t, 1, DD);
    mlp2_kernel<<<192, 256, 0, s2>>>(p_h1t, t2w, t2b, p_xt,  0, DD);
    mlp2_kernel<<<192, 256, 0, s2>>>(p_xt,  pw,  pb,  p_hb,  0, 2 * DD);
    cudaEventRecord(eB, s2);

    // ---- stream C tail: meta, d-chain (ret_x), complement zero ----
    meta_kernel<<<1, NBOX, 0, s3>>>(bboxes, out_mask);
    cudaEventRecord(eMeta, s3);
    cudaStreamWaitEvent(s3, eMean, 0);
    mlp2_kernel<<<192, 256, 0, s3>>>(p_x,   d1w, d1b, p_h1d,   1, DD);
    mlp2_kernel<<<192, 256, 0, s3>>>(p_h1d, d2w, d2b, out_retx, 0, DD);
    zero_comp_kernel<<<512, 256, 0, s3>>>((float4*)out_vis);
    cudaEventRecord(eC, s3);

    // ---- stream A: conv0 -> gemm0 -> (wait WC) -> fused split-K gemm -> epi ----
    conv0_kernel<<<448, 256>>>(m1w, features);
    hgemm<<<dim3(16, 12, 1), 256, GEMM_SMEM>>>(0, m1b);
    cudaStreamWaitEvent(0, eWC, 0);
    hgemm<<<dim3(16, 12, SPLITK), 256, GEMM_SMEM>>>(2, nullptr);

    cudaStreamWaitEvent(0, eB, 0);
    cudaStreamWaitEvent(0, eMeta, 0);
    epi_kernel<<<NBOX, 192>>>(bboxes, out_vis);

    cudaStreamWaitEvent(0, eC, 0);
}

// round 17
// speedup vs baseline: 1.0951x; 1.0951x over previous
#include <cuda_runtime.h>
#include <cuda_fp16.h>
#include <cstdint>

// Problem constants
#define BB 16
#define TT 4096
#define DD 768
#define NBOX 1024
#define MAXB 128
#define DDETR 256
#define VIS_ELEMS (BB*MAXB*DD)
#define MASK_ELEMS (BB*MAXB)
#define NC 64

// ---------------- scratch (device globals) -----------------------------------
__device__ __align__(16) float g_partial[BB*NC*DD];
__device__ __align__(16) float g_x[BB*DD];
__device__ __align__(16) float g_h1t[BB*DD];
__device__ __align__(16) float g_h1d[BB*DD];
__device__ __align__(16) float g_xt[BB*DD];
__device__ __align__(16) float g_hb[BB*DD];
__device__ __align__(16) float g_hacc[NBOX*DD];      // gemm2 partial (z=0)
__device__ __align__(16) float g_hacc2[NBOX*DD];     // gemm2 partial (z=1)
__device__ __align__(16) float g_wcacc0[768*768];    // gemmWC partial (z=0)
__device__ __align__(16) float g_wcacc1[768*768];    // gemmWC partial (z=1)
__device__ __align__(16) float g_cb[DD];             // pw2 @ m2b  (NO pb here!)
__device__ int g_pos[NBOX];
__device__ int g_counts[BB];

// fp16 hi/lo operand arrays (row-major, k contiguous)
__device__ __align__(16) __half g_w1h[768*256],  g_w1l[768*256];
__device__ __align__(16) __half g_wph[768*768],  g_wpl[768*768];   // pw[:,768:]
__device__ __align__(16) __half g_w2th[768*768], g_w2tl[768*768];  // m2w^T
__device__ __align__(16) __half g_wch[768*768],  g_wcl[768*768];   // WC = pw2@m2w
__device__ __align__(16) __half g_feath[1024*256], g_featl[1024*256];
__device__ __align__(16) __half g_fm1h[1024*768],  g_fm1l[1024*768];

// ---------------- helpers -------------------------------------------------------
__device__ __forceinline__ uint32_t smem_u32(const void* p) {
    uint32_t r;
    asm("{ .reg .u64 t; cvta.to.shared.u64 t, %1; cvt.u32.u64 %0, t; }"
        : "=r"(r) : "l"(p));
    return r;
}
#define CP_ASYNC16(dst, src) \
    asm volatile("cp.async.cg.shared.global [%0], [%1], 16;" \
                 :: "r"(dst), "l"(src) : "memory")
#define CP_COMMIT() asm volatile("cp.async.commit_group;" ::: "memory")
#define CP_WAIT(n)  asm volatile("cp.async.wait_group %0;" :: "n"(n) : "memory")

#define LDSM_X4(r0, r1, r2, r3, addr) \
    asm volatile("ldmatrix.sync.aligned.m8n8.x4.shared.b16 {%0,%1,%2,%3}, [%4];" \
                 : "=r"(r0), "=r"(r1), "=r"(r2), "=r"(r3) : "r"(addr))

#define MMA16816(acc, a0, a1, a2, a3, b0, b1) \
    asm volatile("mma.sync.aligned.m16n8k16.row.col.f32.f16.f16.f32 " \
                 "{%0,%1,%2,%3}, {%4,%5,%6,%7}, {%8,%9}, {%0,%1,%2,%3};" \
                 : "+f"((acc)[0]), "+f"((acc)[1]), "+f"((acc)[2]), "+f"((acc)[3]) \
                 : "r"(a0), "r"(a1), "r"(a2), "r"(a3), "r"(b0), "r"(b1))

__device__ __forceinline__ void h2split(float v, __half2* oh, __half2* ol,
                                        float v1) {
    __half h0 = __float2half_rn(v),  h1 = __float2half_rn(v1);
    __half l0 = __float2half_rn(v - __half2float(h0));
    __half l1 = __float2half_rn(v1 - __half2float(h1));
    *oh = __halves2half2(h0, h1);
    *ol = __halves2half2(l0, l1);
}

// ---------------- segment metadata (tiny) ----------------------------------------
__global__ void meta_kernel(const int* __restrict__ bboxes,
                            float* __restrict__ att_mask_out) {
    __shared__ int counts[BB];
    __shared__ int offs[BB];
    int t = threadIdx.x;
    if (t < BB) counts[t] = 0;
    __syncthreads();
    int im = bboxes[t * 5];
    atomicAdd(&counts[im], 1);
    __syncthreads();
    if (t == 0) {
        int s = 0;
        for (int b = 0; b < BB; b++) { offs[b] = s; s += counts[b]; }
    }
    __syncthreads();
    g_pos[t] = t - offs[im];
    if (t < BB) g_counts[t] = counts[t];
    for (int i = t; i < BB * MAXB; i += NBOX) {
        int b = i / MAXB, m = i % MAXB;
        att_mask_out[i] = (m < counts[b]) ? 1.0f : 0.0f;
    }
}

// ---------------- zero ONLY complement slots -------------------------------------
__global__ void zero_comp_kernel(float4* __restrict__ out) {
    const int n4 = VIS_ELEMS / 4;
    for (int i = blockIdx.x * blockDim.x + threadIdx.x; i < n4;
         i += gridDim.x * blockDim.x) {
        int row = i / 192;
        int b = row >> 7, m = row & 127;
        if (m >= g_counts[b])
            out[i] = make_float4(0.f, 0.f, 0.f, 0.f);
    }
}

// ---------------- epilogue: vis[img,pos] = hacc + hacc2 + hb[img] + cb -----------
__global__ void epi_kernel(const int* __restrict__ bboxes,
                           float* __restrict__ out_vis) {
    int n = blockIdx.x;
    int p = g_pos[n];
    if (p >= MAXB) return;
    int im = bboxes[n * 5];
    int c4 = threadIdx.x * 4;
    float4 a  = *reinterpret_cast<const float4*>(&g_hacc[(size_t)n * DD + c4]);
    float4 a2 = *reinterpret_cast<const float4*>(&g_hacc2[(size_t)n * DD + c4]);
    float4 b  = *reinterpret_cast<const float4*>(&g_hb[im * DD + c4]);
    float4 c  = *reinterpret_cast<const float4*>(&g_cb[c4]);
    a.x += a2.x + b.x + c.x; a.y += a2.y + b.y + c.y;
    a.z += a2.z + b.z + c.z; a.w += a2.w + b.w + c.w;
    *reinterpret_cast<float4*>(&out_vis[((size_t)im * MAXB + p) * DD + c4]) = a;
}

// ---------------- mean pass 1 ----------------------------------------------------
__global__ void mean_partial_kernel(const float* __restrict__ in) {
    int b = blockIdx.x >> 6;
    int c = blockIdx.x & 63;
    const float4* p = reinterpret_cast<const float4*>(
        in + ((size_t)b * TT + (size_t)c * 64) * DD) + threadIdx.x;
    float4 acc = make_float4(0.f, 0.f, 0.f, 0.f);
    #pragma unroll 8
    for (int r = 0; r < 64; r++) {
        float4 v = p[(size_t)r * (DD / 4)];
        acc.x += v.x; acc.y += v.y; acc.z += v.z; acc.w += v.w;
    }
    reinterpret_cast<float4*>(g_partial + ((size_t)b * NC + c) * DD)[threadIdx.x] = acc;
}

// ---------------- mean pass 2: warp per float4 output ----------------------------
__global__ void mean_final_kernel() {
    int W = blockIdx.x * 8 + (threadIdx.x >> 5);
    int lane = threadIdx.x & 31;
    int b  = W / 192;
    int c4 = W - b * 192;
    const float4* base = reinterpret_cast<const float4*>(g_partial)
                         + (size_t)b * NC * 192 + c4;
    float4 v0 = base[(size_t)lane * 192];
    float4 v1 = base[(size_t)(lane + 32) * 192];
    float sx = v0.x + v1.x, sy = v0.y + v1.y, sz = v0.z + v1.z, sw = v0.w + v1.w;
#pragma unroll
    for (int off = 16; off > 0; off >>= 1) {
        sx += __shfl_xor_sync(0xFFFFFFFFu, sx, off);
        sy += __shfl_xor_sync(0xFFFFFFFFu, sy, off);
        sz += __shfl_xor_sync(0xFFFFFFFFu, sz, off);
        sw += __shfl_xor_sync(0xFFFFFFFFu, sw, off);
    }
    if (lane == 0) {
        const float s = 1.0f / (float)TT;
        reinterpret_cast<float4*>(g_x)[(size_t)b * 192 + c4] =
            make_float4(sx * s, sy * s, sz * s, sw * s);
    }
}

// ---------------- small GEMV: no smem staging, k-split 2, grid 192 ----------------
__global__ __launch_bounds__(256) void mlp2_kernel(
        const float* __restrict__ in, const float* __restrict__ w,
        const float* __restrict__ bias, float* __restrict__ out,
        int do_relu, int wstride) {
    __shared__ float sp[4][2][BB];
    const int tid = threadIdx.x, warp = tid >> 5, lane = tid & 31;
    const int col = warp >> 1, kh = warp & 1;
    const int j = blockIdx.x * 4 + col;
    const float* wr = w + (size_t)j * wstride + kh * 384;

    float4 wv[3];
#pragma unroll
    for (int i = 0; i < 3; i++)
        wv[i] = *reinterpret_cast<const float4*>(&wr[i * 128 + lane * 4]);

    float acc[BB];
#pragma unroll
    for (int b = 0; b < BB; b++) acc[b] = 0.f;
#pragma unroll
    for (int i = 0; i < 3; i++) {
        int k = kh * 384 + i * 128 + lane * 4;
#pragma unroll
        for (int b = 0; b < BB; b++) {
            float4 xv = __ldg(reinterpret_cast<const float4*>(&in[b * DD + k]));
            acc[b] = fmaf(wv[i].x, xv.x, acc[b]);
            acc[b] = fmaf(wv[i].y, xv.y, acc[b]);
            acc[b] = fmaf(wv[i].z, xv.z, acc[b]);
            acc[b] = fmaf(wv[i].w, xv.w, acc[b]);
        }
    }
#pragma unroll
    for (int b = 0; b < BB; b++) {
#pragma unroll
        for (int off = 16; off > 0; off >>= 1)
            acc[b] += __shfl_xor_sync(0xFFFFFFFFu, acc[b], off);
    }
    if (lane == 0) {
#pragma unroll
        for (int b = 0; b < BB; b++) sp[col][kh][b] = acc[b];
    }
    __syncthreads();
    if (tid < 64) {
        int c = tid >> 4, b = tid & 15;
        int jj = blockIdx.x * 4 + c;
        float v = sp[c][0][b] + sp[c][1][b] + bias[jj];
        if (do_relu) v = fmaxf(v, 0.f);
        out[b * DD + jj] = v;
    }
}

// ---------------- merged: pw2 split + cb = pw2@m2b --------------------------------
// grid 384: all blocks do grid-stride pw2 split; blocks 0..95 also compute cb.
__global__ void convpcb_kernel(const float* __restrict__ pw,
                               const float* __restrict__ m2b) {
    const int TOT = 768 * 768;
    for (int i = blockIdx.x * blockDim.x + threadIdx.x; i < TOT;
         i += gridDim.x * blockDim.x) {
        int col = i / 768, k = i - col * 768;
        float v = pw[(size_t)col * (2 * DD) + DD + k];
        __half h = __float2half_rn(v);
        g_wph[i] = h;
        g_wpl[i] = __float2half_rn(v - __half2float(h));
    }
    if (blockIdx.x < 96) {
        int warp = threadIdx.x >> 5, lane = threadIdx.x & 31;
        int j = blockIdx.x * 8 + warp;
        const float* wr = pw + (size_t)j * (2 * DD) + DD;
        float acc = 0.f;
#pragma unroll
        for (int i = 0; i < 6; i++) {
            float4 w4 = *reinterpret_cast<const float4*>(&wr[i * 128 + lane * 4]);
            float4 b4 = *reinterpret_cast<const float4*>(&m2b[i * 128 + lane * 4]);
            acc += w4.x * b4.x + w4.y * b4.y + w4.z * b4.z + w4.w * b4.w;
        }
#pragma unroll
        for (int off = 16; off > 0; off >>= 1)
            acc += __shfl_xor_sync(0xFFFFFFFFu, acc, off);
        if (lane == 0) g_cb[j] = acc;      // NOTE: pb is added by the hb chain
    }
}

// ---------------- convert: w1 + feat split ----------------------------------------
#define CN1 (768*256)
#define CN4 (1024*256)
__global__ void conv0_kernel(const float* __restrict__ m1w,
                             const float* __restrict__ feat) {
    const int TOT = CN1 + CN4;
    for (int i = blockIdx.x * blockDim.x + threadIdx.x; i < TOT;
         i += gridDim.x * blockDim.x) {
        float v; __half *oh, *ol; int o;
        if (i < CN1) { o = i; v = m1w[o]; oh = g_w1h; ol = g_w1l; }
        else {
            o = i - CN1;
            int n = o >> 8, k = o & 255;
            v = feat[(size_t)n * (DDETR + 1) + 1 + k];
            oh = g_feath; ol = g_featl;
        }
        __half h = __float2half_rn(v);
        oh[o] = h;
        ol[o] = __float2half_rn(v - __half2float(h));
    }
}
// ---------------- transpose + split m2w -> g_w2th/g_w2tl --------------------------
__global__ void w2t_kernel(const float* __restrict__ m2w) {
    __shared__ float tile[32][33];
    int bx = blockIdx.x, by = blockIdx.y;
    int tx = threadIdx.x & 31, tr = threadIdx.x >> 5;
    for (int r = tr; r < 32; r += 8)
        tile[r][tx] = m2w[(size_t)(by * 32 + r) * 768 + bx * 32 + tx];
    __syncthreads();
    for (int r = tr; r < 32; r += 8) {
        float v = tile[tx][r];
        size_t o = (size_t)(bx * 32 + r) * 768 + by * 32 + tx;
        __half h = __float2half_rn(v);
        g_w2th[o] = h;
        g_w2tl[o] = __float2half_rn(v - __half2float(h));
    }
}

// ---------------- WC reduce: sum partials, split to hi/lo -------------------------
__global__ void wcsplit_kernel() {
    const int TOT = 768 * 768;
    for (int i = blockIdx.x * blockDim.x + threadIdx.x; i < TOT;
         i += gridDim.x * blockDim.x) {
        float v = g_wcacc0[i] + g_wcacc1[i];
        __half h = __float2half_rn(v);
        g_wch[i] = h;
        g_wcl[i] = __float2half_rn(v - __half2float(h));
    }
}

// ---------------- fp16 split GEMM: 3-stage cp.async, split-K x2 (R14 config) -------
// mode 0: fm1 = relu(feat @ m1w^T + m1b)   K=256, grid(16,12,1) -> hi/lo
// mode 2: hacc[z] = fm1 @ WC^T (half K)    K=768, grid(16,12,2) -> raw fp32
// mode 3: wcacc[z] = pw2 @ m2wT (half K)   K=768, grid(12,12,2) -> raw fp32
#define NSTG 3
#define ARRB (64*20*4)
#define STGB (4*ARRB)
#define GEMM_SMEM (NSTG*STGB)    // 61440
__global__ __launch_bounds__(256) void hgemm(int mode,
        const float* __restrict__ bias) {
    extern __shared__ __align__(16) uint32_t S[];

    const int tid = threadIdx.x;
    const int bm = blockIdx.x, bn = blockIdx.y, bz = blockIdx.z;
    const int wid = tid >> 5, lane = tid & 31, gid = lane >> 2, tig = lane & 3;
    const int wm = wid >> 2, wn = wid & 3;
    const int K = (mode == 0) ? 256 : 768;
    const int K2 = K >> 1;                       // row stride in uint32
    const int Keff = K / gridDim.z;
    const int nch = Keff / 32;
    const int kb2 = bz * (Keff >> 1);            // k offset in uint32

    const __half *Ahp, *Alp, *Bhp, *Blp;
    if (mode == 0)      { Ahp = g_feath; Alp = g_featl; Bhp = g_w1h;  Blp = g_w1l;  }
    else if (mode == 2) { Ahp = g_fm1h;  Alp = g_fm1l;  Bhp = g_wch;  Blp = g_wcl;  }
    else                { Ahp = g_wph;   Alp = g_wpl;   Bhp = g_w2th; Blp = g_w2tl; }

    const uint32_t* gsrc[4];
    gsrc[0] = (const uint32_t*)Ahp + (size_t)(bm * 64) * K2 + kb2;
    gsrc[1] = (const uint32_t*)Alp + (size_t)(bm * 64) * K2 + kb2;
    gsrc[2] = (const uint32_t*)Bhp + (size_t)(bn * 64) * K2 + kb2;
    gsrc[3] = (const uint32_t*)Blp + (size_t)(bn * 64) * K2 + kb2;

    const uint32_t sbase = smem_u32(S);

    const int q = lane >> 3, lm = lane & 7;
    const uint32_t offA = (uint32_t)(((wm * 32 + lm + (q & 1) * 8) * 20
                                      + ((q >> 1) * 4)) * 4);
    const uint32_t offB = (uint32_t)(((wn * 16 + lm + (q >> 1) * 8) * 20
                                      + ((q & 1) * 4)) * 4);

    float acc[2][2][4];
#pragma unroll
    for (int mt = 0; mt < 2; mt++)
#pragma unroll
        for (int nt = 0; nt < 2; nt++)
#pragma unroll
            for (int x = 0; x < 4; x++) acc[mt][nt][x] = 0.f;

#define LOAD_CHUNK(ch, st) do {                                              \
        int _kc2 = (ch) * 16;                                                \
        _Pragma("unroll")                                                    \
        for (int _i = 0; _i < 4; _i++) {                                     \
            int _id = tid + _i * 256;                                        \
            int _arr = _id >> 8;                                             \
            int _rem = _id & 255;                                            \
            int _row = _rem >> 2, _seg = _rem & 3;                           \
            const uint32_t* _gp = gsrc[_arr] + (size_t)_row * K2 + _kc2 + _seg * 4; \
            uint32_t _dst = sbase + (st) * STGB + _arr * ARRB                \
                            + (_row * 20 + _seg * 4) * 4;                    \
            CP_ASYNC16(_dst, _gp);                                           \
        }                                                                    \
    } while (0)

#pragma unroll
    for (int s = 0; s < NSTG - 1; s++) {
        LOAD_CHUNK(s, s);
        CP_COMMIT();
    }

    for (int c = 0; c < nch; c++) {
        CP_WAIT(NSTG - 2);
        __syncthreads();
        if (c + NSTG - 1 < nch) {
            int st = (c + NSTG - 1) % NSTG;
            LOAD_CHUNK(c + NSTG - 1, st);
        }
        CP_COMMIT();

        const uint32_t stb = sbase + (c % NSTG) * STGB;
#pragma unroll
        for (int ks = 0; ks < 2; ks++) {
            uint32_t ah0[4], ah1[4], al0[4], al1[4], bh[4], bl[4];
            LDSM_X4(ah0[0], ah0[1], ah0[2], ah0[3], stb + offA + ks * 32);
            LDSM_X4(ah1[0], ah1[1], ah1[2], ah1[3], stb + offA + 1280 + ks * 32);
            LDSM_X4(al0[0], al0[1], al0[2], al0[3], stb + ARRB + offA + ks * 32);
            LDSM_X4(al1[0], al1[1], al1[2], al1[3], stb + ARRB + offA + 1280 + ks * 32);
            LDSM_X4(bh[0],  bh[1],  bh[2],  bh[3],  stb + 2 * ARRB + offB + ks * 32);
            LDSM_X4(bl[0],  bl[1],  bl[2],  bl[3],  stb + 3 * ARRB + offB + ks * 32);
#pragma unroll
            for (int nt = 0; nt < 2; nt++) {
                uint32_t b0 = bh[nt * 2], b1 = bh[nt * 2 + 1];
                uint32_t c0 = bl[nt * 2], c1 = bl[nt * 2 + 1];
                MMA16816(acc[0][nt], ah0[0], ah0[1], ah0[2], ah0[3], b0, b1);
                MMA16816(acc[1][nt], ah1[0], ah1[1], ah1[2], ah1[3], b0, b1);
                MMA16816(acc[0][nt], al0[0], al0[1], al0[2], al0[3], b0, b1);
                MMA16816(acc[1][nt], al1[0], al1[1], al1[2], al1[3], b0, b1);
                MMA16816(acc[0][nt], ah0[0], ah0[1], ah0[2], ah0[3], c0, c1);
                MMA16816(acc[1][nt], ah1[0], ah1[1], ah1[2], ah1[3], c0, c1);
            }
        }
    }
#undef LOAD_CHUNK

    const int col00 = bn * 64 + wn * 16;
    if (mode != 0) {
        float* dst = (mode == 2) ? (bz ? g_hacc2 : g_hacc)
                                 : (bz ? g_wcacc1 : g_wcacc0);
#pragma unroll
        for (int nt = 0; nt < 2; nt++) {
            int col = col00 + nt * 8 + tig * 2;
#pragma unroll
            for (int mt = 0; mt < 2; mt++) {
                int r = bm * 64 + wm * 32 + mt * 16 + gid;
                float* d0 = &dst[(size_t)r * DD + col];
                d0[0] = acc[mt][nt][0];
                d0[1] = acc[mt][nt][1];
                float* d1 = &dst[(size_t)(r + 8) * DD + col];
                d1[0] = acc[mt][nt][2];
                d1[1] = acc[mt][nt][3];
            }
        }
    } else {
#pragma unroll
        for (int nt = 0; nt < 2; nt++) {
            int col = col00 + nt * 8 + tig * 2;
            float bv0 = bias[col], bv1 = bias[col + 1];
#pragma unroll
            for (int mt = 0; mt < 2; mt++) {
                int r = bm * 64 + wm * 32 + mt * 16 + gid;
                float v00 = fmaxf(acc[mt][nt][0] + bv0, 0.f);
                float v01 = fmaxf(acc[mt][nt][1] + bv1, 0.f);
                float v10 = fmaxf(acc[mt][nt][2] + bv0, 0.f);
                float v11 = fmaxf(acc[mt][nt][3] + bv1, 0.f);
                __half2 hp, lp;
                h2split(v00, &hp, &lp, v01);
                *(__half2*)&g_fm1h[(size_t)r * DD + col] = hp;
                *(__half2*)&g_fm1l[(size_t)r * DD + col] = lp;
                h2split(v10, &hp, &lp, v11);
                *(__half2*)&g_fm1h[(size_t)(r + 8) * DD + col] = hp;
                *(__half2*)&g_fm1l[(size_t)(r + 8) * DD + col] = lp;
            }
        }
    }
}

// ---------------- launch: 3-stream graph, split-K x2 GEMMs -------------------------
extern "C" void kernel_launch(void* const* d_in, const int* in_sizes, int n_in,
                              void* d_out, int out_size) {
    (void)in_sizes; (void)n_in; (void)out_size;
    const float* inputs   = (const float*)d_in[0];
    const int*   bboxes   = (const int*)  d_in[1];
    const float* features = (const float*)d_in[2];
    const float* t1w = (const float*)d_in[3],  *t1b = (const float*)d_in[4];
    const float* t2w = (const float*)d_in[5],  *t2b = (const float*)d_in[6];
    const float* d1w = (const float*)d_in[7],  *d1b = (const float*)d_in[8];
    const float* d2w = (const float*)d_in[9],  *d2b = (const float*)d_in[10];
    const float* m1w = (const float*)d_in[11], *m1b = (const float*)d_in[12];
    const float* m2w = (const float*)d_in[13], *m2b = (const float*)d_in[14];
    const float* pw  = (const float*)d_in[15], *pb  = (const float*)d_in[16];

    float* out      = (float*)d_out;
    float* out_vis  = out;
    float* out_mask = out + VIS_ELEMS;
    float* out_retx = out + VIS_ELEMS + MASK_ELEMS;

    cudaFuncSetAttribute(hgemm, cudaFuncAttributeMaxDynamicSharedMemorySize,
                         GEMM_SMEM);

    static cudaStream_t s2 = nullptr, s3 = nullptr;
    static cudaEvent_t eFork = nullptr, eMean = nullptr, eMeta = nullptr,
                       eB = nullptr, eC = nullptr, eWC = nullptr;
    static float *p_x, *p_h1t, *p_h1d, *p_xt, *p_hb;
    if (s2 == nullptr) {
        cudaStreamCreateWithFlags(&s2, cudaStreamNonBlocking);
        cudaStreamCreateWithFlags(&s3, cudaStreamNonBlocking);
        cudaEventCreateWithFlags(&eFork, cudaEventDisableTiming);
        cudaEventCreateWithFlags(&eMean, cudaEventDisableTiming);
        cudaEventCreateWithFlags(&eMeta, cudaEventDisableTiming);
        cudaEventCreateWithFlags(&eB, cudaEventDisableTiming);
        cudaEventCreateWithFlags(&eC, cudaEventDisableTiming);
        cudaEventCreateWithFlags(&eWC, cudaEventDisableTiming);
        cudaGetSymbolAddress((void**)&p_x,    g_x);
        cudaGetSymbolAddress((void**)&p_h1t,  g_h1t);
        cudaGetSymbolAddress((void**)&p_h1d,  g_h1d);
        cudaGetSymbolAddress((void**)&p_xt,   g_xt);
        cudaGetSymbolAddress((void**)&p_hb,   g_hb);
    }

    // fork
    cudaEventRecord(eFork, 0);
    cudaStreamWaitEvent(s2, eFork, 0);
    cudaStreamWaitEvent(s3, eFork, 0);

    // launch order puts gemmWC 6th (profiled by ncu -s 5 -c 1)
    mean_partial_kernel<<<BB * NC, 192, 0, s2>>>(inputs);            // 1 (B)
    meta_kernel<<<1, NBOX, 0, s3>>>(bboxes, out_mask);               // 2 (C)
    cudaEventRecord(eMeta, s3);
    convpcb_kernel<<<384, 256, 0, s3>>>(pw, m2b);                    // 3 (C)
    w2t_kernel<<<dim3(24, 24), 256, 0, s3>>>(m2w);                   // 4 (C)
    mean_final_kernel<<<384, 256, 0, s2>>>();                        // 5 (B)
    cudaEventRecord(eMean, s2);
    hgemm<<<dim3(12, 12, 2), 256, GEMM_SMEM, s3>>>(3, nullptr);      // 6 (C) <- prof
    wcsplit_kernel<<<576, 256, 0, s3>>>();                           // 7 (C)
    cudaEventRecord(eWC, s3);

    // ---- stream B: t-chain -> hb ----
    mlp2_kernel<<<192, 256, 0, s2>>>(p_x,   t1w, t1b, p_h1t, 1, DD);
    mlp2_kernel<<<192, 256, 0, s2>>>(p_h1t, t2w, t2b, p_xt,  0, DD);
    mlp2_kernel<<<192, 256, 0, s2>>>(p_xt,  pw,  pb,  p_hb,  0, 2 * DD);
    cudaEventRecord(eB, s2);

    // ---- stream C tail: d-chain (ret_x), complement zero ----
    cudaStreamWaitEvent(s3, eMean, 0);
    mlp2_kernel<<<192, 256, 0, s3>>>(p_x,   d1w, d1b, p_h1d,   1, DD);
    mlp2_kernel<<<192, 256, 0, s3>>>(p_h1d, d2w, d2b, out_retx, 0, DD);
    zero_comp_kernel<<<512, 256, 0, s3>>>((float4*)out_vis);
    cudaEventRecord(eC, s3);

    // ---- stream A: conv0 -> gemm0 -> (wait WC) -> fused split-K gemm -> epi ----
    conv0_kernel<<<448, 256>>>(m1w, features);
    hgemm<<<dim3(16, 12, 1), 256, GEMM_SMEM>>>(0, m1b);
    cudaStreamWaitEvent(0, eWC, 0);
    hgemm<<<dim3(16, 12, 2), 256, GEMM_SMEM>>>(2, nullptr);

    cudaStreamWaitEvent(0, eB, 0);
    cudaStreamWaitEvent(0, eMeta, 0);
    epi_kernel<<<NBOX, 192>>>(bboxes, out_vis);

    cudaStreamWaitEvent(0, eC, 0);
}